// round 9
// baseline (speedup 1.0000x reference)
#include <cuda_runtime.h>
#include <cstdint>

#define TSTEPS 128
#define BATCH  1024
#define HID    512
#define G4     2048
#define FUTN   32

#define NCTA   128
#define NTHR   512          // 16 warps
#define KT     64           // K-chunk in floats
#define ROWB   272          // padded row stride (256B data + 16B pad)
#define TILE_B (128 * ROWB) // 34816 B per operand tile
#define STG_B  (2 * TILE_B) // A + B per stage
#define NSTG   3
#define SMEM_BYTES (NSTG * STG_B)   // 208896 B dynamic

enum { MODE_NONE = -1, MODE_L1 = 0, MODE_L2 = 1, MODE_PRE = 2, MODE_FUTA = 3 };

// ---------------- device globals (static scratch) ----------------
__device__ float g_hcat[2][BATCH][1024];   // [buf][b][0:512]=h1, [512:1024]=h2
__device__ float g_c1[BATCH][HID];
__device__ float g_c2[BATCH][HID];
__device__ float g_W1r[G4][HID];           // Whh1 rows reordered r'=4j+gate, tf32-rounded
__device__ float g_W2cat[G4][1024];        // [Wih2r | Whh2r], tf32-rounded
__device__ float g_Wih1r[G4][4];           // Wih1 reordered (full fp32, used in epilogue FMA)
__device__ float g_b1r[G4];
__device__ float g_b2r[G4];
__device__ float g_prefut[BATCH][G4];
__device__ unsigned g_bar_cnt, g_bar_gen;
__device__ unsigned g_grp_cnt[8][32];      // one monotonic counter per row-group, 128B apart

// ---------------- helpers ----------------
__device__ __forceinline__ float tf32r(float x) {
    asm("cvt.rna.tf32.f32 %0, %1;" : "=f"(x) : "f"(x));
    return x;
}
__device__ __forceinline__ float sigm(float v) {
    return __fdividef(1.f, 1.f + __expf(-v));
}
__device__ __forceinline__ float tanh_f(float v) {
    return __fdividef(2.f, 1.f + __expf(-2.f * v)) - 1.f;
}

__device__ __forceinline__ void cp16(uint32_t s, const float* g) {
    asm volatile("cp.async.cg.shared.global [%0], [%1], 16;" :: "r"(s), "l"(g));
}
#define CP_COMMIT() asm volatile("cp.async.commit_group;" ::)
#define CP_WAIT1()  asm volatile("cp.async.wait_group 1;" ::)
#define CP_WAIT0()  asm volatile("cp.async.wait_group 0;" ::)

__device__ __forceinline__ void ldsm4(uint32_t* r, uint32_t a) {
    asm volatile("ldmatrix.sync.aligned.m8n8.x4.shared.b16 {%0,%1,%2,%3}, [%4];"
                 : "=r"(r[0]), "=r"(r[1]), "=r"(r[2]), "=r"(r[3]) : "r"(a));
}
__device__ __forceinline__ void ldsm2(uint32_t* r, uint32_t a) {
    asm volatile("ldmatrix.sync.aligned.m8n8.x2.shared.b16 {%0,%1}, [%2];"
                 : "=r"(r[0]), "=r"(r[1]) : "r"(a));
}
__device__ __forceinline__ void mma8(float* c, const uint32_t* a, const uint32_t* b) {
    asm volatile(
        "mma.sync.aligned.m16n8k8.row.col.f32.tf32.tf32.f32 "
        "{%0,%1,%2,%3}, {%4,%5,%6,%7}, {%8,%9}, {%0,%1,%2,%3};\n"
        : "+f"(c[0]), "+f"(c[1]), "+f"(c[2]), "+f"(c[3])
        : "r"(a[0]), "r"(a[1]), "r"(a[2]), "r"(a[3]), "r"(b[0]), "r"(b[1]));
}

// Full grid barrier (init only).
__device__ __forceinline__ void grid_bar() {
    __threadfence();
    __syncthreads();
    if (threadIdx.x == 0) {
        unsigned gen = atomicAdd(&g_bar_gen, 0u);
        unsigned t = atomicAdd(&g_bar_cnt, 1u);
        if (t == NCTA - 1) {
            atomicExch(&g_bar_cnt, 0u);
            atomicAdd(&g_bar_gen, 1u);
        } else {
            while (atomicAdd(&g_bar_gen, 0u) == gen) { __nanosleep(64); }
        }
        __threadfence();
    }
    __syncthreads();
}

// Group barrier: 16 CTAs sharing a 128-row batch block. Monotonic counter,
// release-arrive + acquire-poll. No L1 flush: cross-CTA data (h) moves via
// cp.async.cg / __ldcg (L2-only); c-state / prefut / Wih1r are CTA-private
// or read-only.
__device__ __forceinline__ void group_bar(unsigned* ctr, unsigned target) {
    __syncthreads();
    if (threadIdx.x == 0) {
        asm volatile("red.release.gpu.global.add.u32 [%0], %1;" :: "l"(ctr), "r"(1u) : "memory");
        unsigned v;
        do {
            asm volatile("ld.acquire.gpu.global.u32 %0, [%1];" : "=r"(v) : "l"(ctr) : "memory");
        } while ((int)(v - target) < 0);
    }
    __syncthreads();
}

// ---------------- fused LSTM epilogue ----------------
// acc[mt][nt][0..3] = (r0,gc),(r0,gc+1),(r0+8,gc),(r0+8,gc+1), gc = 4j+gate cols.
// All 32 lanes compute cells: even lane -> row r0, odd lane -> row r0+8.
template <int MODE>
__device__ __forceinline__ void epilogue(float acc[2][4][4], int t, int p,
                                         int m0, int c0, int wm, int wn,
                                         int gid, int tig,
                                         const float* __restrict__ x)
{
    float* hOut; float* cS;
    if (MODE == MODE_L1 || MODE == MODE_FUTA) { hOut = &g_hcat[1 - p][0][0];   cS = &g_c1[0][0]; }
    else                                      { hOut = &g_hcat[1 - p][0][512]; cS = &g_c2[0][0]; }

    // pre-terms
#pragma unroll
    for (int mt = 0; mt < 2; mt++) {
        int r0 = m0 + wm * 32 + mt * 16 + gid;
        float4 x0, x1;
        if (MODE == MODE_L1) {
            x0 = *(const float4*)(x + ((size_t)t * BATCH + r0) * 4);
            x1 = *(const float4*)(x + ((size_t)t * BATCH + r0 + 8) * 4);
        }
#pragma unroll
        for (int nt = 0; nt < 4; nt++) {
            int gc = c0 + wn * 32 + nt * 8 + 2 * tig;
            if (MODE == MODE_L1) {
                float2 b = *(const float2*)&g_b1r[gc];
                float4 w0 = *(const float4*)&g_Wih1r[gc][0];
                float4 w1 = *(const float4*)&g_Wih1r[gc + 1][0];
                acc[mt][nt][0] += b.x + x0.x * w0.x + x0.y * w0.y + x0.z * w0.z + x0.w * w0.w;
                acc[mt][nt][1] += b.y + x0.x * w1.x + x0.y * w1.y + x0.z * w1.z + x0.w * w1.w;
                acc[mt][nt][2] += b.x + x1.x * w0.x + x1.y * w0.y + x1.z * w0.z + x1.w * w0.w;
                acc[mt][nt][3] += b.y + x1.x * w1.x + x1.y * w1.y + x1.z * w1.z + x1.w * w1.w;
            } else if (MODE == MODE_FUTA) {
                float2 p0 = *(const float2*)&g_prefut[r0][gc];
                float2 p1 = *(const float2*)&g_prefut[r0 + 8][gc];
                acc[mt][nt][0] += p0.x; acc[mt][nt][1] += p0.y;
                acc[mt][nt][2] += p1.x; acc[mt][nt][3] += p1.y;
            } else { // L2 / PRE
                float2 b = *(const float2*)&g_b2r[gc];
                acc[mt][nt][0] += b.x; acc[mt][nt][1] += b.y;
                acc[mt][nt][2] += b.x; acc[mt][nt][3] += b.y;
            }
        }
    }

    if (MODE == MODE_PRE) {
#pragma unroll
        for (int mt = 0; mt < 2; mt++) {
            int r0 = m0 + wm * 32 + mt * 16 + gid;
#pragma unroll
            for (int nt = 0; nt < 4; nt++) {
                int gc = c0 + wn * 32 + nt * 8 + 2 * tig;
                *(float2*)&g_prefut[r0][gc]     = make_float2(acc[mt][nt][0], acc[mt][nt][1]);
                *(float2*)&g_prefut[r0 + 8][gc] = make_float2(acc[mt][nt][2], acc[mt][nt][3]);
            }
        }
        return;
    }

    const bool odd = (tig & 1);
#pragma unroll
    for (int mt = 0; mt < 2; mt++) {
        int r0 = m0 + wm * 32 + mt * 16 + gid;
#pragma unroll
        for (int nt = 0; nt < 4; nt++) {
            // even lane sends its (r0+8) pair, odd lane sends its r0 pair
            float s0 = odd ? acc[mt][nt][0] : acc[mt][nt][2];
            float s1 = odd ? acc[mt][nt][1] : acc[mt][nt][3];
            float u0 = __shfl_xor_sync(0xffffffffu, s0, 1);
            float u1 = __shfl_xor_sync(0xffffffffu, s1, 1);
            float gi = odd ? u0 : acc[mt][nt][0];
            float gf = odd ? u1 : acc[mt][nt][1];
            float gg = odd ? acc[mt][nt][2] : u0;
            float go = odd ? acc[mt][nt][3] : u1;
            int row = odd ? (r0 + 8) : r0;
            int j = ((c0 + wn * 32 + nt * 8) >> 2) + (tig >> 1);
            float co = cS[(size_t)row * HID + j];
            float cn = sigm(gf) * co + sigm(gi) * tanh_f(gg);
            float hn = sigm(go) * tanh_f(cn);
            cS[(size_t)row * HID + j] = cn;
            hOut[(size_t)row * 1024 + j] = tf32r(hn);
        }
    }
}

// ---------------- fused double-GEMM phase ----------------
// Runs sub-GEMM MA (NKA chunks) then sub-GEMM MB (NKB chunks) through ONE
// continuous cp.async ring (one __syncthreads per 64-float chunk), with
// epilogue<MA> overlapped against sub-B's loads. One group barrier per phase.
template <int MA, int MB>
__device__ void gemm_phase(int t, int p, uint32_t smem_u, const float* __restrict__ x)
{
    const int tid = threadIdx.x;
    const int m0 = (blockIdx.x >> 4) * 128;
    const int c0 = (blockIdx.x & 15) * 128;
    constexpr int NKA = (MA == MODE_L2) ? 16 : 8;
    constexpr int NKB = (MB == MODE_NONE) ? 0 : ((MB == MODE_L2) ? 16 : 8);
    constexpr int NKT = NKA + NKB;

    const int lane = tid & 31, gid = lane >> 2, tig = lane & 3;
    const int warp = tid >> 5, wm = warp >> 2, wn = warp & 3;
    const int rA = (lane & 7) + ((lane >> 3) & 1) * 8;
    const int cA = (lane >> 4) * 16;
    const int lb = lane & 15;
    const int rB = lb & 7;
    const int cB = (lb >> 3) * 16;

    float acc[2][4][4];
#pragma unroll
    for (int a = 0; a < 2; a++)
#pragma unroll
        for (int b = 0; b < 4; b++)
#pragma unroll
            for (int c = 0; c < 4; c++) acc[a][b][c] = 0.f;

    auto prefetch = [&](int c) {
        int mode, ci;
        if (c < NKA) { mode = MA; ci = c; } else { mode = MB; ci = c - NKA; }
        const float* As = &g_hcat[p][m0][((mode == MODE_PRE) ? 512 : 0) + ci * KT];
        const float* Bs; int Bl;
        if (mode == MODE_L1) { Bs = &g_W1r[c0][ci * KT]; Bl = 512; }
        else { Bs = &g_W2cat[c0][((mode == MODE_FUTA) ? 512 : 0) + ci * KT]; Bl = 1024; }
        uint32_t sa = smem_u + (c % NSTG) * STG_B;
        uint32_t sb = sa + TILE_B;
#pragma unroll
        for (int i = 0; i < 4; i++) {
            int idx = i * NTHR + tid;          // 0..2047
            int r = idx >> 4, kc = idx & 15;   // row, 16B piece within 256B row
            cp16(sa + r * ROWB + kc * 16, As + (size_t)r * 1024 + kc * 4);
            cp16(sb + r * ROWB + kc * 16, Bs + (size_t)r * Bl + kc * 4);
        }
        CP_COMMIT();
    };

    prefetch(0); prefetch(1);

#pragma unroll 1
    for (int c = 0; c < NKT; c++) {
        if (c + 1 < NKT) CP_WAIT1(); else CP_WAIT0();
        __syncthreads();                 // stage c ready; stage (c+2)%3 free
        if (c + 2 < NKT) prefetch(c + 2);

        const uint32_t sa = smem_u + (c % NSTG) * STG_B;
        const uint32_t sb = sa + TILE_B;
#pragma unroll
        for (int k8 = 0; k8 < KT / 8; k8++) {
            uint32_t af[2][4], bf[4][2];
#pragma unroll
            for (int mt = 0; mt < 2; mt++)
                ldsm4(af[mt], sa + (wm * 32 + mt * 16 + rA) * ROWB + k8 * 32 + cA);
#pragma unroll
            for (int nt = 0; nt < 4; nt++)
                ldsm2(bf[nt], sb + (wn * 32 + nt * 8 + rB) * ROWB + k8 * 32 + cB);
#pragma unroll
            for (int mt = 0; mt < 2; mt++)
#pragma unroll
                for (int nt = 0; nt < 4; nt++) mma8(acc[mt][nt], af[mt], bf[nt]);
        }

        if (NKB > 0 && c == NKA - 1) {
            epilogue<MA>(acc, t, p, m0, c0, wm, wn, gid, tig, x);
#pragma unroll
            for (int a = 0; a < 2; a++)
#pragma unroll
                for (int b = 0; b < 4; b++)
#pragma unroll
                    for (int cc = 0; cc < 4; cc++) acc[a][b][cc] = 0.f;
        }
    }
    epilogue<(MB == MODE_NONE) ? MA : MB>(acc, t, p, m0, c0, wm, wn, gid, tig, x);
}

// Forward a 128x32 h-slice (this CTA's column slice of its row block) from
// buf[p] to buf[1-p], L2-only path. Needed at the main->future seam.
__device__ void copy_slice(int p, int colbase)
{
    const int tm = blockIdx.x >> 4, tn = blockIdx.x & 15;
#pragma unroll
    for (int i = 0; i < 2; i++) {
        int idx = i * NTHR + threadIdx.x;      // 0..1023
        int r = idx >> 3, q = idx & 7;         // 128 rows x 8 float4
        const float4* s = (const float4*)&g_hcat[p][tm * 128 + r][colbase + tn * 32 + q * 4];
        float4 v = __ldcg(s);
        __stcg((float4*)&g_hcat[1 - p][tm * 128 + r][colbase + tn * 32 + q * 4], v);
    }
}

// Per-CTA output GEMV: CTA (tm,tn) handles 8 batch rows of its own block.
__device__ void out_gemv(const float* __restrict__ h2, const float* __restrict__ Wl,
                         const float* __restrict__ bl, float* __restrict__ out, int t)
{
    const int tid = threadIdx.x;
    const int tm = blockIdx.x >> 4, tn = blockIdx.x & 15;
    const int oi = tid >> 4;           // 0..31: 8 rows x 4 outs
    const int sub = tid & 15;
    const int b = tm * 128 + tn * 8 + (oi >> 2);
    const int o = oi & 3;
    const float* hr = h2 + (size_t)b * 1024 + sub * 32;
    const float* wr = Wl + o * HID + sub * 32;
    float s = 0.f;
#pragma unroll
    for (int k = 0; k < 32; k += 4) {
        float4 hv = __ldcg((const float4*)(hr + k));
        float4 wv = *(const float4*)(wr + k);
        s += hv.x * wv.x + hv.y * wv.y + hv.z * wv.z + hv.w * wv.w;
    }
    s += __shfl_xor_sync(0xffffffffu, s, 8);
    s += __shfl_xor_sync(0xffffffffu, s, 4);
    s += __shfl_xor_sync(0xffffffffu, s, 2);
    s += __shfl_xor_sync(0xffffffffu, s, 1);
    if (sub == 0) out[((size_t)t * BATCH + b) * 4 + o] = s + bl[o];
}

__global__ void __launch_bounds__(NTHR, 1)
lstm_kernel(const float* __restrict__ x,
            const float* __restrict__ Wih1, const float* __restrict__ Whh1,
            const float* __restrict__ bih1, const float* __restrict__ bhh1,
            const float* __restrict__ Wih2, const float* __restrict__ Whh2,
            const float* __restrict__ bih2, const float* __restrict__ bhh2,
            const float* __restrict__ Wl, const float* __restrict__ bl,
            float* __restrict__ out)
{
    extern __shared__ __align__(128) char smem[];
    const uint32_t smem_u = (uint32_t)__cvta_generic_to_shared(smem);
    const int tid = threadIdx.x;
    const int gtid = blockIdx.x * NTHR + tid;
    const int nth = NCTA * NTHR;

    // ---- init scratch (deterministic every launch) ----
    for (int i = gtid; i < BATCH * 2048; i += nth) (&g_hcat[0][0][0])[i] = 0.f;
    for (int i = gtid; i < BATCH * HID; i += nth) { (&g_c1[0][0])[i] = 0.f; (&g_c2[0][0])[i] = 0.f; }
    for (int i = gtid; i < G4 * HID; i += nth) {
        int r = i >> 9, k = i & 511, j = r >> 2, g = r & 3;
        g_W1r[r][k] = tf32r(Whh1[(size_t)(g * 512 + j) * 512 + k]);
    }
    for (int i = gtid; i < G4 * 1024; i += nth) {
        int r = i >> 10, k = i & 1023, j = r >> 2, g = r & 3;
        float v = (k < 512) ? Wih2[(size_t)(g * 512 + j) * 512 + k]
                            : Whh2[(size_t)(g * 512 + j) * 512 + (k - 512)];
        g_W2cat[r][k] = tf32r(v);
    }
    for (int r = gtid; r < G4; r += nth) {
        int j = r >> 2, g = r & 3;
        g_b1r[r] = bih1[g * 512 + j] + bhh1[g * 512 + j];
        g_b2r[r] = bih2[g * 512 + j] + bhh2[g * 512 + j];
        *(float4*)&g_Wih1r[r][0] = *(const float4*)&Wih1[(size_t)(g * 512 + j) * 4];
    }
    grid_bar();   // full fence: weights/x now safe to cache anywhere

    // ---- group barrier setup (monotonic across graph replays) ----
    unsigned* const grp_ctr = &g_grp_cnt[blockIdx.x >> 4][0];
    unsigned bar_base = 0;
    if (tid == 0) {
        asm volatile("ld.acquire.gpu.global.u32 %0, [%1];" : "=r"(bar_base) : "l"(grp_ctr) : "memory");
    }
    unsigned phn = 0;
#define GB() group_bar(grp_ctr, bar_base + 16u * (++phn))

    int p = 0;
    // phase 0: L1(0) alone
    gemm_phase<MODE_L1, MODE_NONE>(0, p, smem_u, x); GB(); p ^= 1;
    // phases 1..127: L1(t) fused with L2(t-1)
    for (int t = 1; t < TSTEPS; t++) {
        gemm_phase<MODE_L1, MODE_L2>(t, p, smem_u, x); GB(); p ^= 1;
    }
    // phase 128: L2(127) alone; forward h1(127) into the other buffer
    copy_slice(p, 0);
    gemm_phase<MODE_L2, MODE_NONE>(0, p, smem_u, x); GB(); p ^= 1;
    // phase 129: PRE fused with FUTA(0) (prefut is thread-private between them);
    // forward h2(127) for FUTL2(0) next phase
    copy_slice(p, 512);
    gemm_phase<MODE_PRE, MODE_FUTA>(0, p, smem_u, x); GB(); p ^= 1;
    // phases 130..160: FUTA(s) fused with FUTL2(s-1); emit out rows as they settle
    for (int s = 1; s < FUTN; s++) {
        if (s >= 2) out_gemv(&g_hcat[p][0][512], Wl, bl, out, s - 2);
        gemm_phase<MODE_FUTA, MODE_L2>(0, p, smem_u, x); GB(); p ^= 1;
    }
    // phase 161: FUTL2(31) alone
    out_gemv(&g_hcat[p][0][512], Wl, bl, out, FUTN - 2);
    gemm_phase<MODE_L2, MODE_NONE>(0, p, smem_u, x); GB(); p ^= 1;
    out_gemv(&g_hcat[p][0][512], Wl, bl, out, FUTN - 1);
#undef GB
}

extern "C" void kernel_launch(void* const* d_in, const int* in_sizes, int n_in,
                              void* d_out, int out_size)
{
    (void)in_sizes; (void)n_in; (void)out_size;
    cudaFuncSetAttribute(lstm_kernel, cudaFuncAttributeMaxDynamicSharedMemorySize, SMEM_BYTES);
    lstm_kernel<<<NCTA, NTHR, SMEM_BYTES>>>(
        (const float*)d_in[0],
        (const float*)d_in[1], (const float*)d_in[2],
        (const float*)d_in[3], (const float*)d_in[4],
        (const float*)d_in[5], (const float*)d_in[6],
        (const float*)d_in[7], (const float*)d_in[8],
        (const float*)d_in[9], (const float*)d_in[10],
        (float*)d_out);
}

// round 10
// speedup vs baseline: 1.1010x; 1.1010x over previous
#include <cuda_runtime.h>
#include <cuda.h>
#include <cstdint>

#define TSTEPS 128
#define BATCH  1024
#define HID    512
#define G4     2048
#define FUTN   32

#define NCTA   128
#define NTHR   512          // 16 warps
#define KT     32           // K-chunk in floats (128B rows)
#define HDR    1024         // smem header: mbarriers
#define TILE_B 16384        // one operand tile: 128 rows x 128B, SW128
#define STG_B  (2 * TILE_B) // A + B per stage
#define NSTG   4
#define SMEM_BYTES (HDR + NSTG * STG_B)   // 132096

enum { MODE_L1 = 0, MODE_L2 = 1, MODE_PRE = 2, MODE_FUTA = 3 };

// ---------------- device globals (static scratch) ----------------
__device__ __align__(1024) float g_hcat[2][BATCH][1024]; // [buf][b][0:512]=h1,[512:1024]=h2
__device__ __align__(1024) float g_W1r[G4][HID];         // Whh1 rows r'=4j+gate, tf32
__device__ __align__(1024) float g_W2cat[G4][1024];      // [Wih2r | Whh2r], tf32
__device__ float g_c1[BATCH][HID];
__device__ float g_c2[BATCH][HID];
__device__ float g_Wih1r[G4][4];           // Wih1 reordered (fp32, epilogue FMA)
__device__ float g_b1r[G4];
__device__ float g_b2r[G4];
__device__ float g_prefut[BATCH][G4];
__device__ unsigned g_bar_cnt, g_bar_gen;
__device__ unsigned g_grp_cnt[8][32];      // per row-group monotonic counter, 128B apart

// ---------------- helpers ----------------
__device__ __forceinline__ float tf32r(float x) {
    asm("cvt.rna.tf32.f32 %0, %1;" : "=f"(x) : "f"(x));
    return x;
}
__device__ __forceinline__ float sigm(float v) { return __fdividef(1.f, 1.f + __expf(-v)); }
__device__ __forceinline__ float tanh_f(float v) { return __fdividef(2.f, 1.f + __expf(-2.f * v)) - 1.f; }

#define SWZ(o) ((o) ^ (((o) >> 3) & 0x70))

__device__ __forceinline__ void ldsm4(uint32_t* r, uint32_t a) {
    asm volatile("ldmatrix.sync.aligned.m8n8.x4.shared.b16 {%0,%1,%2,%3}, [%4];"
                 : "=r"(r[0]), "=r"(r[1]), "=r"(r[2]), "=r"(r[3]) : "r"(a));
}
__device__ __forceinline__ void ldsm2(uint32_t* r, uint32_t a) {
    asm volatile("ldmatrix.sync.aligned.m8n8.x2.shared.b16 {%0,%1}, [%2];"
                 : "=r"(r[0]), "=r"(r[1]) : "r"(a));
}
__device__ __forceinline__ void mma8(float* c, const uint32_t* a, const uint32_t* b) {
    asm volatile(
        "mma.sync.aligned.m16n8k8.row.col.f32.tf32.tf32.f32 "
        "{%0,%1,%2,%3}, {%4,%5,%6,%7}, {%8,%9}, {%0,%1,%2,%3};\n"
        : "+f"(c[0]), "+f"(c[1]), "+f"(c[2]), "+f"(c[3])
        : "r"(a[0]), "r"(a[1]), "r"(a[2]), "r"(a[3]), "r"(b[0]), "r"(b[1]));
}

__device__ __forceinline__ void tma3d(uint32_t smem, const CUtensorMap* m,
                                      int x0, int y0, int z0, uint32_t mb) {
    asm volatile(
        "cp.async.bulk.tensor.3d.shared::cta.global.tile.mbarrier::complete_tx::bytes "
        "[%0], [%1, {%2, %3, %4}], [%5];"
        :: "r"(smem), "l"(m), "r"(x0), "r"(y0), "r"(z0), "r"(mb) : "memory");
}
__device__ __forceinline__ void tma2d(uint32_t smem, const CUtensorMap* m,
                                      int x0, int y0, uint32_t mb) {
    asm volatile(
        "cp.async.bulk.tensor.2d.shared::cta.global.tile.mbarrier::complete_tx::bytes "
        "[%0], [%1, {%2, %3}], [%4];"
        :: "r"(smem), "l"(m), "r"(x0), "r"(y0), "r"(mb) : "memory");
}

#define MBARRIER_INIT(mb, c) \
    asm volatile("mbarrier.init.shared.b64 [%0], %1;" :: "r"((uint32_t)(mb)), "r"((uint32_t)(c)) : "memory")
#define MBARRIER_INVAL(mb) \
    asm volatile("mbarrier.inval.shared.b64 [%0];" :: "r"((uint32_t)(mb)) : "memory")
#define MBARRIER_EXPECT_TX(mb, tx) \
    asm volatile("mbarrier.arrive.expect_tx.shared.b64 _, [%0], %1;" \
                 :: "r"((uint32_t)(mb)), "r"((uint32_t)(tx)) : "memory")
#define FENCE_PROXY_ASYNC() asm volatile("fence.proxy.async;" ::: "memory")

#define MBARRIER_WAIT_PARITY(mb, par) do { \
    uint32_t _mb = (uint32_t)(mb); \
    uint32_t _p  = (uint32_t)(par); \
    uint32_t _done; \
    asm volatile( \
        "{\n\t.reg .pred p;\n\t" \
        "mbarrier.try_wait.parity.acquire.cta.shared::cta.b64 p, [%1], %2;\n\t" \
        "selp.b32 %0, 1, 0, p;\n\t}" \
        : "=r"(_done) : "r"(_mb), "r"(_p) : "memory"); \
    if (!_done) { \
        asm volatile( \
            "{\n\t.reg .pred P1;\n\t" \
            "WL_%=:\n\t" \
            "mbarrier.try_wait.parity.acquire.cta.shared::cta.b64 P1, [%0], %1, 0x989680;\n\t" \
            "@P1 bra.uni WD_%=;\n\t" \
            "bra.uni WL_%=;\n\t" \
            "WD_%=:\n\t}" \
            :: "r"(_mb), "r"(_p) : "memory"); \
    } \
} while (0)

// Full grid barrier (init only).
__device__ __forceinline__ void grid_bar() {
    FENCE_PROXY_ASYNC();
    __threadfence();
    __syncthreads();
    if (threadIdx.x == 0) {
        unsigned gen = atomicAdd(&g_bar_gen, 0u);
        unsigned t = atomicAdd(&g_bar_cnt, 1u);
        if (t == NCTA - 1) {
            atomicExch(&g_bar_cnt, 0u);
            atomicAdd(&g_bar_gen, 1u);
        } else {
            while (atomicAdd(&g_bar_gen, 0u) == gen) { __nanosleep(64); }
        }
        __threadfence();
    }
    __syncthreads();
}

// Group barrier: 16 CTAs sharing a 128-row batch block. Monotonic counter,
// release-arrive + acquire-poll. proxy fence orders generic h-writes before
// the next phase's TMA (async-proxy) reads.
__device__ __forceinline__ void group_bar(unsigned* ctr, unsigned target) {
    FENCE_PROXY_ASYNC();
    __syncthreads();
    if (threadIdx.x == 0) {
        asm volatile("red.release.gpu.global.add.u32 [%0], %1;" :: "l"(ctr), "r"(1u) : "memory");
        unsigned v;
        do {
            asm volatile("ld.acquire.gpu.global.u32 %0, [%1];" : "=r"(v) : "l"(ctr) : "memory");
        } while ((int)(v - target) < 0);
    }
    __syncthreads();
}

// ---------------- fused LSTM epilogue ----------------
// acc[mt][nt][0..3] = (r0,gc),(r0,gc+1),(r0+8,gc),(r0+8,gc+1), gc = 4j+gate.
// All 32 lanes compute cells: even lane -> row r0, odd lane -> row r0+8.
template <int MODE>
__device__ __forceinline__ void epilogue(float acc[2][4][4], int t, int p,
                                         int m0, int c0, int wm, int wn,
                                         int gid, int tig,
                                         const float* __restrict__ x)
{
    float* hOut; float* cS;
    if (MODE == MODE_L1 || MODE == MODE_FUTA) { hOut = &g_hcat[1 - p][0][0];   cS = &g_c1[0][0]; }
    else                                      { hOut = &g_hcat[1 - p][0][512]; cS = &g_c2[0][0]; }

#pragma unroll
    for (int mt = 0; mt < 2; mt++) {
        int r0 = m0 + wm * 32 + mt * 16 + gid;
        float4 x0, x1;
        if (MODE == MODE_L1) {
            x0 = *(const float4*)(x + ((size_t)t * BATCH + r0) * 4);
            x1 = *(const float4*)(x + ((size_t)t * BATCH + r0 + 8) * 4);
        }
#pragma unroll
        for (int nt = 0; nt < 4; nt++) {
            int gc = c0 + wn * 32 + nt * 8 + 2 * tig;
            if (MODE == MODE_L1) {
                float2 b = *(const float2*)&g_b1r[gc];
                float4 w0 = *(const float4*)&g_Wih1r[gc][0];
                float4 w1 = *(const float4*)&g_Wih1r[gc + 1][0];
                acc[mt][nt][0] += b.x + x0.x * w0.x + x0.y * w0.y + x0.z * w0.z + x0.w * w0.w;
                acc[mt][nt][1] += b.y + x0.x * w1.x + x0.y * w1.y + x0.z * w1.z + x0.w * w1.w;
                acc[mt][nt][2] += b.x + x1.x * w0.x + x1.y * w0.y + x1.z * w0.z + x1.w * w0.w;
                acc[mt][nt][3] += b.y + x1.x * w1.x + x1.y * w1.y + x1.z * w1.z + x1.w * w1.w;
            } else if (MODE == MODE_FUTA) {
                float2 p0 = *(const float2*)&g_prefut[r0][gc];
                float2 p1 = *(const float2*)&g_prefut[r0 + 8][gc];
                acc[mt][nt][0] += p0.x; acc[mt][nt][1] += p0.y;
                acc[mt][nt][2] += p1.x; acc[mt][nt][3] += p1.y;
            } else { // L2 / PRE
                float2 b = *(const float2*)&g_b2r[gc];
                acc[mt][nt][0] += b.x; acc[mt][nt][1] += b.y;
                acc[mt][nt][2] += b.x; acc[mt][nt][3] += b.y;
            }
        }
    }

    if (MODE == MODE_PRE) {
#pragma unroll
        for (int mt = 0; mt < 2; mt++) {
            int r0 = m0 + wm * 32 + mt * 16 + gid;
#pragma unroll
            for (int nt = 0; nt < 4; nt++) {
                int gc = c0 + wn * 32 + nt * 8 + 2 * tig;
                *(float2*)&g_prefut[r0][gc]     = make_float2(acc[mt][nt][0], acc[mt][nt][1]);
                *(float2*)&g_prefut[r0 + 8][gc] = make_float2(acc[mt][nt][2], acc[mt][nt][3]);
            }
        }
        return;
    }

    const bool odd = (tig & 1);
#pragma unroll
    for (int mt = 0; mt < 2; mt++) {
        int r0 = m0 + wm * 32 + mt * 16 + gid;
#pragma unroll
        for (int nt = 0; nt < 4; nt++) {
            float s0 = odd ? acc[mt][nt][0] : acc[mt][nt][2];
            float s1 = odd ? acc[mt][nt][1] : acc[mt][nt][3];
            float u0 = __shfl_xor_sync(0xffffffffu, s0, 1);
            float u1 = __shfl_xor_sync(0xffffffffu, s1, 1);
            float gi = odd ? u0 : acc[mt][nt][0];
            float gf = odd ? u1 : acc[mt][nt][1];
            float gg = odd ? acc[mt][nt][2] : u0;
            float go = odd ? acc[mt][nt][3] : u1;
            int row = odd ? (r0 + 8) : r0;
            int j = ((c0 + wn * 32 + nt * 8) >> 2) + (tig >> 1);
            float co = cS[(size_t)row * HID + j];
            float cn = sigm(gf) * co + sigm(gi) * tanh_f(gg);
            float hn = sigm(go) * tanh_f(cn);
            cS[(size_t)row * HID + j] = cn;
            hOut[(size_t)row * 1024 + j] = tf32r(hn);
        }
    }
}

// ---------------- one GEMM phase (TMA-fed) + fused LSTM epilogue ----------------
// Tile: rows m0..m0+127 (batch), cols c0..c0+127 (gate cols r'=4j+gate).
// D = A @ B^T over NK K-chunks of 32 floats; loads via TMA, one mbarrier/stage.
template <int MODE>
__device__ void gemm_phase(int t, int p, uint32_t smem_u, unsigned& G,
                           const CUtensorMap* tmH, const CUtensorMap* tmW1,
                           const CUtensorMap* tmW2, const float* __restrict__ x)
{
    const int tid = threadIdx.x;
    const int m0 = (blockIdx.x >> 4) * 128;
    const int c0 = (blockIdx.x & 15) * 128;
    constexpr int NK = (MODE == MODE_L2) ? 32 : 16;

    const int lane = tid & 31, gid = lane >> 2, tig = lane & 3;
    const int warp = tid >> 5, wm = warp >> 2, wn = warp & 3;
    const int rA = (lane & 7) + ((lane >> 3) & 1) * 8;
    const int cA = (lane >> 4) * 16;
    const int lb = lane & 15;
    const int rB = lb & 7;
    const int cB = (lb >> 3) * 16;

    float acc[2][4][4];
#pragma unroll
    for (int a = 0; a < 2; a++)
#pragma unroll
        for (int b = 0; b < 4; b++)
#pragma unroll
            for (int c = 0; c < 4; c++) acc[a][b][c] = 0.f;

    auto produce = [&](int c) {
        if (tid != 0) return;
        unsigned s = (G + c) & 3;
        uint32_t sa = smem_u + HDR + s * STG_B;
        uint32_t sb = sa + TILE_B;
        uint32_t mb = smem_u + 64 + s * 8;
        MBARRIER_EXPECT_TX(mb, 2 * TILE_B);
        int ka, za;
        if (MODE == MODE_L2)       { ka = c * 32;       za = (c < 16) ? (1 - p) : p; }
        else if (MODE == MODE_PRE) { ka = 512 + c * 32; za = p; }
        else                       { ka = c * 32;       za = p; }
        tma3d(sa, tmH, ka, m0, za, mb);
        if (MODE == MODE_L1) tma2d(sb, tmW1, c * 32, c0, mb);
        else                 tma2d(sb, tmW2, ((MODE == MODE_FUTA) ? 512 : 0) + c * 32, c0, mb);
    };

    produce(0); produce(1);

#pragma unroll 1
    for (int c = 0; c < NK; c++) {
        unsigned Gc = G + c;
        MBARRIER_WAIT_PARITY(smem_u + 64 + (Gc & 3) * 8, (Gc >> 2) & 1);
        __syncthreads();                 // all warps at chunk c; stage (Gc+2)&3 reusable
        if (c + 2 < NK) produce(c + 2);

        const uint32_t sa = smem_u + HDR + (Gc & 3) * STG_B;
        const uint32_t sb = sa + TILE_B;
#pragma unroll
        for (int k8 = 0; k8 < KT / 8; k8++) {
            uint32_t af[2][4], bf[4][2];
#pragma unroll
            for (int mt = 0; mt < 2; mt++) {
                uint32_t o = (uint32_t)((wm * 32 + mt * 16 + rA) * 128 + k8 * 32 + cA);
                ldsm4(af[mt], sa + SWZ(o));
            }
#pragma unroll
            for (int nt = 0; nt < 4; nt++) {
                uint32_t o = (uint32_t)((wn * 32 + nt * 8 + rB) * 128 + k8 * 32 + cB);
                ldsm2(bf[nt], sb + SWZ(o));
            }
#pragma unroll
            for (int mt = 0; mt < 2; mt++)
#pragma unroll
                for (int nt = 0; nt < 4; nt++) mma8(acc[mt][nt], af[mt], bf[nt]);
        }
    }
    G += NK;

    epilogue<MODE>(acc, t, p, m0, c0, wm, wn, gid, tig, x);
}

// Per-CTA output GEMV: CTA (tm,tn) handles 8 batch rows of its own block.
__device__ void out_gemv(const float* __restrict__ h2, const float* __restrict__ Wl,
                         const float* __restrict__ bl, float* __restrict__ out, int t)
{
    const int tid = threadIdx.x;
    const int tm = blockIdx.x >> 4, tn = blockIdx.x & 15;
    const int oi = tid >> 4;           // 0..31: 8 rows x 4 outs
    const int sub = tid & 15;
    const int b = tm * 128 + tn * 8 + (oi >> 2);
    const int o = oi & 3;
    const float* hr = h2 + (size_t)b * 1024 + sub * 32;
    const float* wr = Wl + o * HID + sub * 32;
    float s = 0.f;
#pragma unroll
    for (int k = 0; k < 32; k += 4) {
        float4 hv = __ldcg((const float4*)(hr + k));
        float4 wv = *(const float4*)(wr + k);
        s += hv.x * wv.x + hv.y * wv.y + hv.z * wv.z + hv.w * wv.w;
    }
    s += __shfl_xor_sync(0xffffffffu, s, 8);
    s += __shfl_xor_sync(0xffffffffu, s, 4);
    s += __shfl_xor_sync(0xffffffffu, s, 2);
    s += __shfl_xor_sync(0xffffffffu, s, 1);
    if (sub == 0) out[((size_t)t * BATCH + b) * 4 + o] = s + bl[o];
}

__global__ void __launch_bounds__(NTHR, 1)
lstm_kernel(const float* __restrict__ x,
            const float* __restrict__ Wih1, const float* __restrict__ Whh1,
            const float* __restrict__ bih1, const float* __restrict__ bhh1,
            const float* __restrict__ Wih2, const float* __restrict__ Whh2,
            const float* __restrict__ bih2, const float* __restrict__ bhh2,
            const float* __restrict__ Wl, const float* __restrict__ bl,
            float* __restrict__ out,
            const __grid_constant__ CUtensorMap tmH,
            const __grid_constant__ CUtensorMap tmW1,
            const __grid_constant__ CUtensorMap tmW2)
{
    extern __shared__ __align__(1024) char smem[];
    const uint32_t smem_u = (uint32_t)__cvta_generic_to_shared(smem);
    const int tid = threadIdx.x;
    const int gtid = blockIdx.x * NTHR + tid;
    const int nth = NCTA * NTHR;

    // ---- init scratch (deterministic every launch) ----
    for (int i = gtid; i < BATCH * 2048; i += nth) (&g_hcat[0][0][0])[i] = 0.f;
    for (int i = gtid; i < BATCH * HID; i += nth) { (&g_c1[0][0])[i] = 0.f; (&g_c2[0][0])[i] = 0.f; }
    for (int i = gtid; i < G4 * HID; i += nth) {
        int r = i >> 9, k = i & 511, j = r >> 2, g = r & 3;
        g_W1r[r][k] = tf32r(Whh1[(size_t)(g * 512 + j) * 512 + k]);
    }
    for (int i = gtid; i < G4 * 1024; i += nth) {
        int r = i >> 10, k = i & 1023, j = r >> 2, g = r & 3;
        float v = (k < 512) ? Wih2[(size_t)(g * 512 + j) * 512 + k]
                            : Whh2[(size_t)(g * 512 + j) * 512 + (k - 512)];
        g_W2cat[r][k] = tf32r(v);
    }
    for (int r = gtid; r < G4; r += nth) {
        int j = r >> 2, g = r & 3;
        g_b1r[r] = bih1[g * 512 + j] + bhh1[g * 512 + j];
        g_b2r[r] = bih2[g * 512 + j] + bhh2[g * 512 + j];
        *(float4*)&g_Wih1r[r][0] = *(const float4*)&Wih1[(size_t)(g * 512 + j) * 4];
    }

    // ---- mbarrier init ----
    if (tid == 0) {
#pragma unroll
        for (int s = 0; s < NSTG; s++) MBARRIER_INIT(smem_u + 64 + s * 8, 1);
    }
    __syncthreads();
    grid_bar();   // full fence: weights/x/zeros visible to TMA everywhere

    // ---- group barrier setup (monotonic across graph replays) ----
    unsigned* const grp_ctr = &g_grp_cnt[blockIdx.x >> 4][0];
    unsigned bar_base = 0;
    if (tid == 0) {
        asm volatile("ld.acquire.gpu.global.u32 %0, [%1];" : "=r"(bar_base) : "l"(grp_ctr) : "memory");
    }
    unsigned phn = 0;
    unsigned G = 0;
#define GB() group_bar(grp_ctr, bar_base + 16u * (++phn))

    int p = 0;
    // ---- main sequence ----
    for (int t = 0; t < TSTEPS; t++) {
        gemm_phase<MODE_L1>(t, p, smem_u, G, &tmH, &tmW1, &tmW2, x);
        GB();
        gemm_phase<MODE_L2>(t, p, smem_u, G, &tmH, &tmW1, &tmW2, x);
        GB();
        p ^= 1;
    }

    // prefut = tmp_out @ Wih2r^T + b2r (tmp_out = frozen h2)
    gemm_phase<MODE_PRE>(0, p, smem_u, G, &tmH, &tmW1, &tmW2, x);
    GB();

    // ---- future loop ----
    for (int s = 0; s < FUTN; s++) {
        gemm_phase<MODE_FUTA>(0, p, smem_u, G, &tmH, &tmW1, &tmW2, x);
        GB();
        gemm_phase<MODE_L2>(0, p, smem_u, G, &tmH, &tmW1, &tmW2, x);
        GB();
        out_gemv(&g_hcat[1 - p][0][512], Wl, bl, out, s);
        p ^= 1;
    }
#undef GB

    __syncthreads();
    if (tid == 0) {
#pragma unroll
        for (int s = 0; s < NSTG; s++) MBARRIER_INVAL(smem_u + 64 + s * 8);
    }
}

// ---------------- host launcher ----------------
typedef CUresult (*EncodeFn)(CUtensorMap*, CUtensorMapDataType, cuuint32_t, void*,
                             const cuuint64_t*, const cuuint64_t*, const cuuint32_t*,
                             const cuuint32_t*, CUtensorMapInterleave, CUtensorMapSwizzle,
                             CUtensorMapL2promotion, CUtensorMapFloatOOBfill);

extern "C" void kernel_launch(void* const* d_in, const int* in_sizes, int n_in,
                              void* d_out, int out_size)
{
    (void)in_sizes; (void)n_in; (void)out_size;

    void* fn = nullptr;
    cudaDriverEntryPointQueryResult qres;
    cudaGetDriverEntryPoint("cuTensorMapEncodeTiled", &fn, cudaEnableDefault, &qres);
    EncodeFn enc = (EncodeFn)fn;

    void *pH = nullptr, *pW1 = nullptr, *pW2 = nullptr;
    cudaGetSymbolAddress(&pH, g_hcat);
    cudaGetSymbolAddress(&pW1, g_W1r);
    cudaGetSymbolAddress(&pW2, g_W2cat);

    CUtensorMap tmH{}, tmW1{}, tmW2{};
    {
        cuuint64_t dims[3] = {1024, 1024, 2};
        cuuint64_t strides[2] = {4096ull, 4194304ull};
        cuuint32_t box[3] = {32, 128, 1};
        cuuint32_t es[3] = {1, 1, 1};
        enc(&tmH, CU_TENSOR_MAP_DATA_TYPE_FLOAT32, 3, pH, dims, strides, box, es,
            CU_TENSOR_MAP_INTERLEAVE_NONE, CU_TENSOR_MAP_SWIZZLE_128B,
            CU_TENSOR_MAP_L2_PROMOTION_L2_128B, CU_TENSOR_MAP_FLOAT_OOB_FILL_NONE);
    }
    {
        cuuint64_t dims[2] = {512, 2048};
        cuuint64_t strides[1] = {2048ull};
        cuuint32_t box[2] = {32, 128};
        cuuint32_t es[2] = {1, 1};
        enc(&tmW1, CU_TENSOR_MAP_DATA_TYPE_FLOAT32, 2, pW1, dims, strides, box, es,
            CU_TENSOR_MAP_INTERLEAVE_NONE, CU_TENSOR_MAP_SWIZZLE_128B,
            CU_TENSOR_MAP_L2_PROMOTION_L2_128B, CU_TENSOR_MAP_FLOAT_OOB_FILL_NONE);
    }
    {
        cuuint64_t dims[2] = {1024, 2048};
        cuuint64_t strides[1] = {4096ull};
        cuuint32_t box[2] = {32, 128};
        cuuint32_t es[2] = {1, 1};
        enc(&tmW2, CU_TENSOR_MAP_DATA_TYPE_FLOAT32, 2, pW2, dims, strides, box, es,
            CU_TENSOR_MAP_INTERLEAVE_NONE, CU_TENSOR_MAP_SWIZZLE_128B,
            CU_TENSOR_MAP_L2_PROMOTION_L2_128B, CU_TENSOR_MAP_FLOAT_OOB_FILL_NONE);
    }

    cudaFuncSetAttribute(lstm_kernel, cudaFuncAttributeMaxDynamicSharedMemorySize, SMEM_BYTES);
    lstm_kernel<<<NCTA, NTHR, SMEM_BYTES>>>(
        (const float*)d_in[0],
        (const float*)d_in[1], (const float*)d_in[2],
        (const float*)d_in[3], (const float*)d_in[4],
        (const float*)d_in[5], (const float*)d_in[6],
        (const float*)d_in[7], (const float*)d_in[8],
        (const float*)d_in[9], (const float*)d_in[10],
        (float*)d_out, tmH, tmW1, tmW2);
}

// round 11
// speedup vs baseline: 1.1090x; 1.0073x over previous
#include <cuda_runtime.h>
#include <cstdint>

#define TSTEPS 128
#define BATCH  1024
#define HID    512
#define G4     2048
#define FUTN   32

#define NCTA   128
#define NTHR   512          // 16 warps
#define KT     32           // K-chunk in floats (128B rows, SW128-swizzled)
#define TILE_B 16384        // one operand tile: 128 rows x 128B
#define STG_B  (2 * TILE_B) // A + B per stage
#define NSTG   6
#define SMEM_BYTES (NSTG * STG_B)   // 196608

enum { MODE_L1 = 0, MODE_L2 = 1, MODE_PRE = 2, MODE_FUTA = 3 };

// ---------------- device globals (static scratch) ----------------
__device__ float g_hcat[2][BATCH][1024];   // [buf][b][0:512]=h1, [512:1024]=h2
__device__ float g_c1[BATCH][HID];
__device__ float g_c2[BATCH][HID];
__device__ float g_W1r[G4][HID];           // Whh1 rows reordered r'=4j+gate, tf32-rounded
__device__ float g_W2cat[G4][1024];        // [Wih2r | Whh2r], tf32-rounded
__device__ float g_Wih1r[G4][4];           // Wih1 reordered (fp32, epilogue FMA)
__device__ float g_b1r[G4];
__device__ float g_b2r[G4];
__device__ float g_prefut[BATCH][G4];
__device__ unsigned g_bar_cnt, g_bar_gen;
__device__ unsigned g_grp_cnt[8][32];      // per row-group monotonic counter, 128B apart

// ---------------- helpers ----------------
__device__ __forceinline__ float tf32r(float x) {
    asm("cvt.rna.tf32.f32 %0, %1;" : "=f"(x) : "f"(x));
    return x;
}
__device__ __forceinline__ float sigm(float v) { return __fdividef(1.f, 1.f + __expf(-v)); }
__device__ __forceinline__ float tanh_f(float v) { return __fdividef(2.f, 1.f + __expf(-2.f * v)) - 1.f; }

#define SWZ(o) ((o) ^ (((o) >> 3) & 0x70))

__device__ __forceinline__ void cp16(uint32_t s, const float* g) {
    asm volatile("cp.async.cg.shared.global [%0], [%1], 16;" :: "r"(s), "l"(g));
}
#define CP_COMMIT() asm volatile("cp.async.commit_group;" ::)
#define CP_WAIT2()  asm volatile("cp.async.wait_group 2;" ::)
#define CP_WAIT0()  asm volatile("cp.async.wait_group 0;" ::)

__device__ __forceinline__ void ldsm4(uint32_t* r, uint32_t a) {
    asm volatile("ldmatrix.sync.aligned.m8n8.x4.shared.b16 {%0,%1,%2,%3}, [%4];"
                 : "=r"(r[0]), "=r"(r[1]), "=r"(r[2]), "=r"(r[3]) : "r"(a));
}
__device__ __forceinline__ void ldsm2(uint32_t* r, uint32_t a) {
    asm volatile("ldmatrix.sync.aligned.m8n8.x2.shared.b16 {%0,%1}, [%2];"
                 : "=r"(r[0]), "=r"(r[1]) : "r"(a));
}
__device__ __forceinline__ void mma8(float* c, const uint32_t* a, const uint32_t* b) {
    asm volatile(
        "mma.sync.aligned.m16n8k8.row.col.f32.tf32.tf32.f32 "
        "{%0,%1,%2,%3}, {%4,%5,%6,%7}, {%8,%9}, {%0,%1,%2,%3};\n"
        : "+f"(c[0]), "+f"(c[1]), "+f"(c[2]), "+f"(c[3])
        : "r"(a[0]), "r"(a[1]), "r"(a[2]), "r"(a[3]), "r"(b[0]), "r"(b[1]));
}

// Full grid barrier (init only).
__device__ __forceinline__ void grid_bar() {
    __threadfence();
    __syncthreads();
    if (threadIdx.x == 0) {
        unsigned gen = atomicAdd(&g_bar_gen, 0u);
        unsigned t = atomicAdd(&g_bar_cnt, 1u);
        if (t == NCTA - 1) {
            atomicExch(&g_bar_cnt, 0u);
            atomicAdd(&g_bar_gen, 1u);
        } else {
            while (atomicAdd(&g_bar_gen, 0u) == gen) { __nanosleep(64); }
        }
        __threadfence();
    }
    __syncthreads();
}

// Group barrier: 16 CTAs sharing a 128-row batch block. Monotonic counter,
// release-arrive + acquire-poll. No L1 flush: cross-CTA data (h) moves via
// cp.async.cg / __ldcg (L2-only); c-state / prefut stay CTA-private in L1.
__device__ __forceinline__ void group_bar(unsigned* ctr, unsigned target) {
    __syncthreads();
    if (threadIdx.x == 0) {
        asm volatile("red.release.gpu.global.add.u32 [%0], %1;" :: "l"(ctr), "r"(1u) : "memory");
        unsigned v;
        do {
            asm volatile("ld.acquire.gpu.global.u32 %0, [%1];" : "=r"(v) : "l"(ctr) : "memory");
        } while ((int)(v - target) < 0);
    }
    __syncthreads();
}

// ---------------- fused LSTM epilogue ----------------
// acc[mt][nt][0..3] = (r0,gc),(r0,gc+1),(r0+8,gc),(r0+8,gc+1), gc = 4j+gate.
// All 32 lanes compute cells: even lane -> row r0, odd lane -> row r0+8.
template <int MODE>
__device__ __forceinline__ void epilogue(float acc[2][4][4], int t, int p,
                                         int m0, int c0, int wm, int wn,
                                         int gid, int tig,
                                         const float* __restrict__ x)
{
    float* hOut; float* cS;
    if (MODE == MODE_L1 || MODE == MODE_FUTA) { hOut = &g_hcat[1 - p][0][0];   cS = &g_c1[0][0]; }
    else                                      { hOut = &g_hcat[1 - p][0][512]; cS = &g_c2[0][0]; }

#pragma unroll
    for (int mt = 0; mt < 2; mt++) {
        int r0 = m0 + wm * 32 + mt * 16 + gid;
        float4 x0, x1;
        if (MODE == MODE_L1) {
            x0 = *(const float4*)(x + ((size_t)t * BATCH + r0) * 4);
            x1 = *(const float4*)(x + ((size_t)t * BATCH + r0 + 8) * 4);
        }
#pragma unroll
        for (int nt = 0; nt < 4; nt++) {
            int gc = c0 + wn * 32 + nt * 8 + 2 * tig;
            if (MODE == MODE_L1) {
                float2 b = *(const float2*)&g_b1r[gc];
                float4 w0 = *(const float4*)&g_Wih1r[gc][0];
                float4 w1 = *(const float4*)&g_Wih1r[gc + 1][0];
                acc[mt][nt][0] += b.x + x0.x * w0.x + x0.y * w0.y + x0.z * w0.z + x0.w * w0.w;
                acc[mt][nt][1] += b.y + x0.x * w1.x + x0.y * w1.y + x0.z * w1.z + x0.w * w1.w;
                acc[mt][nt][2] += b.x + x1.x * w0.x + x1.y * w0.y + x1.z * w0.z + x1.w * w0.w;
                acc[mt][nt][3] += b.y + x1.x * w1.x + x1.y * w1.y + x1.z * w1.z + x1.w * w1.w;
            } else if (MODE == MODE_FUTA) {
                float2 p0 = *(const float2*)&g_prefut[r0][gc];
                float2 p1 = *(const float2*)&g_prefut[r0 + 8][gc];
                acc[mt][nt][0] += p0.x; acc[mt][nt][1] += p0.y;
                acc[mt][nt][2] += p1.x; acc[mt][nt][3] += p1.y;
            } else { // L2 / PRE
                float2 b = *(const float2*)&g_b2r[gc];
                acc[mt][nt][0] += b.x; acc[mt][nt][1] += b.y;
                acc[mt][nt][2] += b.x; acc[mt][nt][3] += b.y;
            }
        }
    }

    if (MODE == MODE_PRE) {
#pragma unroll
        for (int mt = 0; mt < 2; mt++) {
            int r0 = m0 + wm * 32 + mt * 16 + gid;
#pragma unroll
            for (int nt = 0; nt < 4; nt++) {
                int gc = c0 + wn * 32 + nt * 8 + 2 * tig;
                *(float2*)&g_prefut[r0][gc]     = make_float2(acc[mt][nt][0], acc[mt][nt][1]);
                *(float2*)&g_prefut[r0 + 8][gc] = make_float2(acc[mt][nt][2], acc[mt][nt][3]);
            }
        }
        return;
    }

    const bool odd = (tig & 1);
#pragma unroll
    for (int mt = 0; mt < 2; mt++) {
        int r0 = m0 + wm * 32 + mt * 16 + gid;
#pragma unroll
        for (int nt = 0; nt < 4; nt++) {
            float s0 = odd ? acc[mt][nt][0] : acc[mt][nt][2];
            float s1 = odd ? acc[mt][nt][1] : acc[mt][nt][3];
            float u0 = __shfl_xor_sync(0xffffffffu, s0, 1);
            float u1 = __shfl_xor_sync(0xffffffffu, s1, 1);
            float gi = odd ? u0 : acc[mt][nt][0];
            float gf = odd ? u1 : acc[mt][nt][1];
            float gg = odd ? acc[mt][nt][2] : u0;
            float go = odd ? acc[mt][nt][3] : u1;
            int row = odd ? (r0 + 8) : r0;
            int j = ((c0 + wn * 32 + nt * 8) >> 2) + (tig >> 1);
            float co = cS[(size_t)row * HID + j];
            float cn = sigm(gf) * co + sigm(gi) * tanh_f(gg);
            float hn = sigm(go) * tanh_f(cn);
            cS[(size_t)row * HID + j] = cn;
            hOut[(size_t)row * 1024 + j] = tf32r(hn);
        }
    }
}

// ---------------- one GEMM phase + fused LSTM epilogue ----------------
// Tile: rows m0..m0+127 (batch), cols c0..c0+127 (gate cols r'=4j+gate).
// D = A @ B^T over NK K-chunks of 32 floats. Pair-processed: two chunks per
// __syncthreads through a 6-stage cp.async ring (SW128-swizzled smem).
template <int MODE>
__device__ void gemm_phase(int t, int p, uint32_t smem_u, const float* __restrict__ x)
{
    const int tid = threadIdx.x;
    const int m0 = (blockIdx.x >> 4) * 128;
    const int c0 = (blockIdx.x & 15) * 128;
    constexpr int NK = (MODE == MODE_L2) ? 32 : 16;

    const int lane = tid & 31, gid = lane >> 2, tig = lane & 3;
    const int warp = tid >> 5, wm = warp >> 2, wn = warp & 3;
    const int rA = (lane & 7) + ((lane >> 3) & 1) * 8;
    const int cA = (lane >> 4) * 16;
    const int lb = lane & 15;
    const int rB = lb & 7;
    const int cB = (lb >> 3) * 16;

    float acc[2][4][4];
#pragma unroll
    for (int a = 0; a < 2; a++)
#pragma unroll
        for (int b = 0; b < 4; b++)
#pragma unroll
            for (int c = 0; c < 4; c++) acc[a][b][c] = 0.f;

    auto prefetch = [&](int c) {
        const float* As; const float* Bs; int Bl;
        if (MODE == MODE_L1)       { As = &g_hcat[p][m0][c * 32];       Bs = &g_W1r[c0][c * 32];           Bl = 512; }
        else if (MODE == MODE_L2)  { int k0 = c * 32;
                                     As = (k0 < 512) ? &g_hcat[1 - p][m0][k0] : &g_hcat[p][m0][k0];
                                     Bs = &g_W2cat[c0][k0];             Bl = 1024; }
        else if (MODE == MODE_FUTA){ As = &g_hcat[p][m0][c * 32];       Bs = &g_W2cat[c0][512 + c * 32];   Bl = 1024; }
        else                       { As = &g_hcat[p][m0][512 + c * 32]; Bs = &g_W2cat[c0][c * 32];         Bl = 1024; }
        uint32_t sa = smem_u + (c % NSTG) * STG_B;
        uint32_t sb = sa + TILE_B;
#pragma unroll
        for (int i = 0; i < 2; i++) {
            int idx = i * NTHR + tid;          // 0..1023
            int r = idx >> 3, kc = idx & 7;    // row, 16B piece within 128B row
            uint32_t off = SWZ((uint32_t)(r * 128 + kc * 16));
            cp16(sa + off, As + (size_t)r * 1024 + kc * 4);
            cp16(sb + off, Bs + (size_t)r * Bl + kc * 4);
        }
        CP_COMMIT();
    };

    auto compute = [&](int c) {
        const uint32_t sa = smem_u + (c % NSTG) * STG_B;
        const uint32_t sb = sa + TILE_B;
#pragma unroll
        for (int k8 = 0; k8 < KT / 8; k8++) {
            uint32_t af[2][4], bf[4][2];
#pragma unroll
            for (int mt = 0; mt < 2; mt++) {
                uint32_t o = (uint32_t)((wm * 32 + mt * 16 + rA) * 128 + k8 * 32 + cA);
                ldsm4(af[mt], sa + SWZ(o));
            }
#pragma unroll
            for (int nt = 0; nt < 4; nt++) {
                uint32_t o = (uint32_t)((wn * 32 + nt * 8 + rB) * 128 + k8 * 32 + cB);
                ldsm2(bf[nt], sb + SWZ(o));
            }
#pragma unroll
            for (int mt = 0; mt < 2; mt++)
#pragma unroll
                for (int nt = 0; nt < 4; nt++) mma8(acc[mt][nt], af[mt], bf[nt]);
        }
    };

    prefetch(0); prefetch(1); prefetch(2); prefetch(3);

#pragma unroll 1
    for (int j = 0; j < NK / 2; j++) {
        const int c = 2 * j;
        if (c + 2 < NK) CP_WAIT2(); else CP_WAIT0();
        __syncthreads();                 // chunks c, c+1 ready; stages of c-2, c-1 free
        if (c + 4 < NK) prefetch(c + 4);
        if (c + 5 < NK) prefetch(c + 5);
        compute(c);
        compute(c + 1);
    }

    epilogue<MODE>(acc, t, p, m0, c0, wm, wn, gid, tig, x);
}

// Per-CTA output GEMV: CTA (tm,tn) handles 8 batch rows of its own block.
__device__ void out_gemv(const float* __restrict__ h2, const float* __restrict__ Wl,
                         const float* __restrict__ bl, float* __restrict__ out, int t)
{
    const int tid = threadIdx.x;
    const int tm = blockIdx.x >> 4, tn = blockIdx.x & 15;
    const int oi = tid >> 4;           // 0..31: 8 rows x 4 outs
    const int sub = tid & 15;
    const int b = tm * 128 + tn * 8 + (oi >> 2);
    const int o = oi & 3;
    const float* hr = h2 + (size_t)b * 1024 + sub * 32;
    const float* wr = Wl + o * HID + sub * 32;
    float s = 0.f;
#pragma unroll
    for (int k = 0; k < 32; k += 4) {
        float4 hv = __ldcg((const float4*)(hr + k));
        float4 wv = *(const float4*)(wr + k);
        s += hv.x * wv.x + hv.y * wv.y + hv.z * wv.z + hv.w * wv.w;
    }
    s += __shfl_xor_sync(0xffffffffu, s, 8);
    s += __shfl_xor_sync(0xffffffffu, s, 4);
    s += __shfl_xor_sync(0xffffffffu, s, 2);
    s += __shfl_xor_sync(0xffffffffu, s, 1);
    if (sub == 0) out[((size_t)t * BATCH + b) * 4 + o] = s + bl[o];
}

__global__ void __launch_bounds__(NTHR, 1)
lstm_kernel(const float* __restrict__ x,
            const float* __restrict__ Wih1, const float* __restrict__ Whh1,
            const float* __restrict__ bih1, const float* __restrict__ bhh1,
            const float* __restrict__ Wih2, const float* __restrict__ Whh2,
            const float* __restrict__ bih2, const float* __restrict__ bhh2,
            const float* __restrict__ Wl, const float* __restrict__ bl,
            float* __restrict__ out)
{
    extern __shared__ __align__(128) char smem[];
    const uint32_t smem_u = (uint32_t)__cvta_generic_to_shared(smem);
    const int tid = threadIdx.x;
    const int gtid = blockIdx.x * NTHR + tid;
    const int nth = NCTA * NTHR;

    // ---- init scratch (deterministic every launch) ----
    for (int i = gtid; i < BATCH * 2048; i += nth) (&g_hcat[0][0][0])[i] = 0.f;
    for (int i = gtid; i < BATCH * HID; i += nth) { (&g_c1[0][0])[i] = 0.f; (&g_c2[0][0])[i] = 0.f; }
    for (int i = gtid; i < G4 * HID; i += nth) {
        int r = i >> 9, k = i & 511, j = r >> 2, g = r & 3;
        g_W1r[r][k] = tf32r(Whh1[(size_t)(g * 512 + j) * 512 + k]);
    }
    for (int i = gtid; i < G4 * 1024; i += nth) {
        int r = i >> 10, k = i & 1023, j = r >> 2, g = r & 3;
        float v = (k < 512) ? Wih2[(size_t)(g * 512 + j) * 512 + k]
                            : Whh2[(size_t)(g * 512 + j) * 512 + (k - 512)];
        g_W2cat[r][k] = tf32r(v);
    }
    for (int r = gtid; r < G4; r += nth) {
        int j = r >> 2, g = r & 3;
        g_b1r[r] = bih1[g * 512 + j] + bhh1[g * 512 + j];
        g_b2r[r] = bih2[g * 512 + j] + bhh2[g * 512 + j];
        *(float4*)&g_Wih1r[r][0] = *(const float4*)&Wih1[(size_t)(g * 512 + j) * 4];
    }
    grid_bar();   // full fence: weights/x/zeros visible everywhere

    // ---- group barrier setup (monotonic across graph replays) ----
    unsigned* const grp_ctr = &g_grp_cnt[blockIdx.x >> 4][0];
    unsigned bar_base = 0;
    if (tid == 0) {
        asm volatile("ld.acquire.gpu.global.u32 %0, [%1];" : "=r"(bar_base) : "l"(grp_ctr) : "memory");
    }
    unsigned phn = 0;
#define GB() group_bar(grp_ctr, bar_base + 16u * (++phn))

    int p = 0;
    // ---- main sequence ----
    for (int t = 0; t < TSTEPS; t++) {
        gemm_phase<MODE_L1>(t, p, smem_u, x);
        GB();
        gemm_phase<MODE_L2>(t, p, smem_u, x);
        GB();
        p ^= 1;
    }

    // prefut = tmp_out @ Wih2r^T + b2r (tmp_out = frozen h2)
    gemm_phase<MODE_PRE>(0, p, smem_u, x);
    GB();

    // ---- future loop ----
    for (int s = 0; s < FUTN; s++) {
        gemm_phase<MODE_FUTA>(0, p, smem_u, x);
        GB();
        gemm_phase<MODE_L2>(0, p, smem_u, x);
        GB();
        out_gemv(&g_hcat[1 - p][0][512], Wl, bl, out, s);
        p ^= 1;
    }
#undef GB
}

extern "C" void kernel_launch(void* const* d_in, const int* in_sizes, int n_in,
                              void* d_out, int out_size)
{
    (void)in_sizes; (void)n_in; (void)out_size;
    cudaFuncSetAttribute(lstm_kernel, cudaFuncAttributeMaxDynamicSharedMemorySize, SMEM_BYTES);
    lstm_kernel<<<NCTA, NTHR, SMEM_BYTES>>>(
        (const float*)d_in[0],
        (const float*)d_in[1], (const float*)d_in[2],
        (const float*)d_in[3], (const float*)d_in[4],
        (const float*)d_in[5], (const float*)d_in[6],
        (const float*)d_in[7], (const float*)d_in[8],
        (const float*)d_in[9], (const float*)d_in[10],
        (float*)d_out);
}

// round 12
// speedup vs baseline: 1.7137x; 1.5452x over previous
#include <cuda_runtime.h>
#include <cstdint>

#define TSTEPS 128
#define BATCH  1024
#define HID    512
#define G4     2048
#define FUTN   32

#define NCTA   128
#define NTHR   512          // 16 warps
#define KT     32           // K-chunk in floats
#define ROWB   144          // padded row stride in bytes (128B data + 16B pad)
#define TILE_B (128 * ROWB) // 18432 B per operand tile
#define STG_B  (2 * TILE_B) // A + B per stage
#define NSTG   4
#define SMEM_BYTES (NSTG * STG_B)   // 147456 B dynamic

enum { MODE_L1 = 0, MODE_FUTA = 1, MODE_L2 = 2, MODE_PRE = 3 };

// ---------------- device globals (static scratch) ----------------
__device__ float g_hcat[2][BATCH][1024];    // [buf][b][0:512]=h1, [512:1024]=h2
__device__ float g_c1[BATCH][HID];
__device__ float g_c2[BATCH][HID];
__device__ float g_W1r[G4][HID];            // Whh1 rows reordered r'=4j+gate, tf32-rounded
__device__ float g_W2cat[G4][1024];         // [Wih2r | Whh2r], tf32-rounded
__device__ float g_W1pad[G4][32];           // Wih1r in cols 0..3, zeros elsewhere
__device__ float g_xpad[TSTEPS][BATCH][32]; // x in cols 0..3 (tf32-rounded), zeros elsewhere
__device__ float g_b1r[G4];
__device__ float g_b2r[G4];
__device__ float g_prefut[BATCH][G4];
__device__ unsigned g_bar_cnt, g_bar_gen;
__device__ unsigned g_grp_cnt[8][32];       // one monotonic counter per row-group, 128B apart

// ---------------- helpers ----------------
__device__ __forceinline__ float tf32r(float x) {
    asm("cvt.rna.tf32.f32 %0, %1;" : "=f"(x) : "f"(x));
    return x;
}
__device__ __forceinline__ float sigm(float v) { return 1.f / (1.f + __expf(-v)); }

__device__ __forceinline__ void cp16(uint32_t s, const float* g) {
    asm volatile("cp.async.cg.shared.global [%0], [%1], 16;" :: "r"(s), "l"(g));
}
#define CP_COMMIT() asm volatile("cp.async.commit_group;" ::)
#define CP_WAIT2()  asm volatile("cp.async.wait_group 2;" ::)
#define CP_WAIT1()  asm volatile("cp.async.wait_group 1;" ::)
#define CP_WAIT0()  asm volatile("cp.async.wait_group 0;" ::)

__device__ __forceinline__ void ldsm4(uint32_t* r, uint32_t a) {
    asm volatile("ldmatrix.sync.aligned.m8n8.x4.shared.b16 {%0,%1,%2,%3}, [%4];"
                 : "=r"(r[0]), "=r"(r[1]), "=r"(r[2]), "=r"(r[3]) : "r"(a));
}
__device__ __forceinline__ void ldsm2(uint32_t* r, uint32_t a) {
    asm volatile("ldmatrix.sync.aligned.m8n8.x2.shared.b16 {%0,%1}, [%2];"
                 : "=r"(r[0]), "=r"(r[1]) : "r"(a));
}
__device__ __forceinline__ void mma8(float* c, const uint32_t* a, const uint32_t* b) {
    asm volatile(
        "mma.sync.aligned.m16n8k8.row.col.f32.tf32.tf32.f32 "
        "{%0,%1,%2,%3}, {%4,%5,%6,%7}, {%8,%9}, {%0,%1,%2,%3};\n"
        : "+f"(c[0]), "+f"(c[1]), "+f"(c[2]), "+f"(c[3])
        : "r"(a[0]), "r"(a[1]), "r"(a[2]), "r"(a[3]), "r"(b[0]), "r"(b[1]));
}

// Full grid barrier (init only).
__device__ __forceinline__ void grid_bar() {
    __threadfence();
    __syncthreads();
    if (threadIdx.x == 0) {
        unsigned gen = atomicAdd(&g_bar_gen, 0u);
        unsigned t = atomicAdd(&g_bar_cnt, 1u);
        if (t == NCTA - 1) {
            atomicExch(&g_bar_cnt, 0u);
            atomicAdd(&g_bar_gen, 1u);
        } else {
            while (atomicAdd(&g_bar_gen, 0u) == gen) { __nanosleep(64); }
        }
        __threadfence();
    }
    __syncthreads();
}

// Group barrier: 16 CTAs sharing a 128-row batch block. Monotonic counter,
// release-arrive + acquire-poll. No L1 flush: cross-CTA data (h) moves via
// cp.async.cg / __ldcg (L2-only); c-state/prefut are CTA-private.
__device__ __forceinline__ void group_bar(unsigned* ctr, unsigned target) {
    __syncthreads();
    if (threadIdx.x == 0) {
        asm volatile("red.release.gpu.global.add.u32 [%0], %1;" :: "l"(ctr), "r"(1u) : "memory");
        unsigned v;
        do {
            asm volatile("ld.acquire.gpu.global.u32 %0, [%1];" : "=r"(v) : "l"(ctr) : "memory");
        } while ((int)(v - target) < 0);
    }
    __syncthreads();
}

// ---------------- one GEMM phase + fused LSTM epilogue (R8-proven) ----------------
// Tile: rows m0..m0+127 (batch block tm), cols c0..c0+127 (gate cols r'=4j+gate).
// D = A @ B^T over NK K-chunks of 32 floats. 16 warps, warp tile 32x32.
template <int MODE>
__device__ void gemm_phase(int t, int p, uint32_t smem_u,
                           float* __restrict__ hOut,    // row stride 1024 floats
                           float* __restrict__ cState)  // row stride 512 floats
{
    const int tid = threadIdx.x;
    const int m0 = (blockIdx.x >> 4) * 128;
    const int c0 = (blockIdx.x & 15) * 128;
    constexpr int NK = (MODE == MODE_L1) ? 17 : (MODE == MODE_L2) ? 32 : 16;

    const int lane = tid & 31, gid = lane >> 2, tig = lane & 3;
    const int warp = tid >> 5, wm = warp >> 2, wn = warp & 3;
    const int rA = (lane & 7) + ((lane >> 3) & 1) * 8;
    const int cA = (lane >> 4) * 16;
    const int lb = lane & 15;
    const int rB = lb & 7;
    const int cB = (lb >> 3) * 16;

    float acc[2][4][4];
#pragma unroll
    for (int a = 0; a < 2; a++)
#pragma unroll
        for (int b = 0; b < 4; b++)
#pragma unroll
            for (int c = 0; c < 4; c++) acc[a][b][c] = 0.f;

    auto prefetch = [&](int c) {
        const float* As; const float* Bs; int Al, Bl;
        if (MODE == MODE_L1) {
            if (c < 16) { As = &g_hcat[p][m0][c * 32]; Al = 1024; Bs = &g_W1r[c0][c * 32]; Bl = 512; }
            else        { As = &g_xpad[t][m0][0];      Al = 32;   Bs = &g_W1pad[c0][0];    Bl = 32; }
        } else if (MODE == MODE_L2) {
            int k0 = c * 32;
            As = (k0 < 512) ? &g_hcat[1 - p][m0][k0] : &g_hcat[p][m0][k0];
            Al = 1024; Bs = &g_W2cat[c0][k0]; Bl = 1024;
        } else if (MODE == MODE_FUTA) {
            As = &g_hcat[p][m0][c * 32]; Al = 1024; Bs = &g_W2cat[c0][512 + c * 32]; Bl = 1024;
        } else { // PRE: A = frozen h2, B = Wih2r half
            As = &g_hcat[p][m0][512 + c * 32]; Al = 1024; Bs = &g_W2cat[c0][c * 32]; Bl = 1024;
        }
        uint32_t sa = smem_u + (c & (NSTG - 1)) * STG_B;
        uint32_t sb = sa + TILE_B;
#pragma unroll
        for (int i = 0; i < 2; i++) {
            int idx = i * NTHR + tid;
            int r = idx >> 3, kc = idx & 7;
            cp16(sa + r * ROWB + kc * 16, As + (size_t)r * Al + kc * 4);
            cp16(sb + r * ROWB + kc * 16, Bs + (size_t)r * Bl + kc * 4);
        }
        CP_COMMIT();
    };

    prefetch(0); prefetch(1); prefetch(2);

#pragma unroll 1
    for (int c = 0; c < NK; c++) {
        if (c + 3 <= NK) CP_WAIT2(); else if (c + 2 == NK) CP_WAIT1(); else CP_WAIT0();
        __syncthreads();                 // stage c ready; stage (c+3)&3 free to refill
        if (c + 3 < NK) prefetch(c + 3);

        const uint32_t sa = smem_u + (c & (NSTG - 1)) * STG_B;
        const uint32_t sb = sa + TILE_B;
#pragma unroll
        for (int k8 = 0; k8 < KT / 8; k8++) {
            uint32_t af[2][4], bf[4][2];
#pragma unroll
            for (int mt = 0; mt < 2; mt++)
                ldsm4(af[mt], sa + (wm * 32 + mt * 16 + rA) * ROWB + k8 * 32 + cA);
#pragma unroll
            for (int nt = 0; nt < 4; nt++)
                ldsm2(bf[nt], sb + (wn * 32 + nt * 8 + rB) * ROWB + k8 * 32 + cB);
#pragma unroll
            for (int mt = 0; mt < 2; mt++)
#pragma unroll
                for (int nt = 0; nt < 4; nt++) mma8(acc[mt][nt], af[mt], bf[nt]);
        }
    }

    // -------- epilogue: pre-terms --------
#pragma unroll
    for (int mt = 0; mt < 2; mt++) {
        int r0 = m0 + wm * 32 + mt * 16 + gid;
#pragma unroll
        for (int nt = 0; nt < 4; nt++) {
            int gc = c0 + wn * 32 + nt * 8 + 2 * tig;
            if (MODE == MODE_FUTA) {
                float2 p0 = *(const float2*)&g_prefut[r0][gc];
                float2 p1 = *(const float2*)&g_prefut[r0 + 8][gc];
                acc[mt][nt][0] += p0.x; acc[mt][nt][1] += p0.y;
                acc[mt][nt][2] += p1.x; acc[mt][nt][3] += p1.y;
            } else {
                const float* bb = (MODE == MODE_L1) ? g_b1r : g_b2r;
                float2 b = *(const float2*)&bb[gc];
                acc[mt][nt][0] += b.x; acc[mt][nt][1] += b.y;
                acc[mt][nt][2] += b.x; acc[mt][nt][3] += b.y;
            }
        }
    }

    if (MODE == MODE_PRE) {
#pragma unroll
        for (int mt = 0; mt < 2; mt++) {
            int r0 = m0 + wm * 32 + mt * 16 + gid;
#pragma unroll
            for (int nt = 0; nt < 4; nt++) {
                int gc = c0 + wn * 32 + nt * 8 + 2 * tig;
                *(float2*)&g_prefut[r0][gc]     = make_float2(acc[mt][nt][0], acc[mt][nt][1]);
                *(float2*)&g_prefut[r0 + 8][gc] = make_float2(acc[mt][nt][2], acc[mt][nt][3]);
            }
        }
        return;
    }

    // -------- epilogue: LSTM cell update --------
    // Columns are r'=4j+gate. Even-tig lane holds (i,f); xor-1 partner holds (g,o).
#pragma unroll
    for (int mt = 0; mt < 2; mt++) {
        int r0 = m0 + wm * 32 + mt * 16 + gid;
#pragma unroll
        for (int nt = 0; nt < 4; nt++) {
            int gc = c0 + wn * 32 + nt * 8 + 2 * tig;
#pragma unroll
            for (int h = 0; h < 2; h++) {
                int row = r0 + 8 * h;
                float v0 = acc[mt][nt][2 * h];
                float v1 = acc[mt][nt][2 * h + 1];
                float q0 = __shfl_xor_sync(0xffffffffu, v0, 1);
                float q1 = __shfl_xor_sync(0xffffffffu, v1, 1);
                if ((tig & 1) == 0) {
                    int j = gc >> 2;
                    float co = cState[(size_t)row * HID + j];
                    float cn = sigm(v1) * co + sigm(v0) * tanhf(q0);
                    float hn = sigm(q1) * tanhf(cn);
                    cState[(size_t)row * HID + j] = cn;
                    hOut[(size_t)row * 1024 + j] = tf32r(hn);
                }
            }
        }
    }
}

// Per-CTA output GEMV: CTA (tm,tn) handles 8 batch rows of its own block.
__device__ void out_gemv(const float* __restrict__ h2, const float* __restrict__ Wl,
                         const float* __restrict__ bl, float* __restrict__ out, int t)
{
    const int tid = threadIdx.x;
    const int tm = blockIdx.x >> 4, tn = blockIdx.x & 15;
    const int oi = tid >> 4;           // 0..31: 8 rows x 4 outs
    const int sub = tid & 15;
    const int b = tm * 128 + tn * 8 + (oi >> 2);
    const int o = oi & 3;
    const float* hr = h2 + (size_t)b * 1024 + sub * 32;
    const float* wr = Wl + o * HID + sub * 32;
    float s = 0.f;
#pragma unroll
    for (int k = 0; k < 32; k += 4) {
        float4 hv = __ldcg((const float4*)(hr + k));
        float4 wv = *(const float4*)(wr + k);
        s += hv.x * wv.x + hv.y * wv.y + hv.z * wv.z + hv.w * wv.w;
    }
    s += __shfl_xor_sync(0xffffffffu, s, 8);
    s += __shfl_xor_sync(0xffffffffu, s, 4);
    s += __shfl_xor_sync(0xffffffffu, s, 2);
    s += __shfl_xor_sync(0xffffffffu, s, 1);
    if (sub == 0) out[((size_t)t * BATCH + b) * 4 + o] = s + bl[o];
}

__global__ void __launch_bounds__(NTHR, 1)
lstm_kernel(const float* __restrict__ x,
            const float* __restrict__ Wih1, const float* __restrict__ Whh1,
            const float* __restrict__ bih1, const float* __restrict__ bhh1,
            const float* __restrict__ Wih2, const float* __restrict__ Whh2,
            const float* __restrict__ bih2, const float* __restrict__ bhh2,
            const float* __restrict__ Wl, const float* __restrict__ bl,
            float* __restrict__ out)
{
    extern __shared__ __align__(128) char smem[];
    const uint32_t smem_u = (uint32_t)__cvta_generic_to_shared(smem);
    const int tid = threadIdx.x;
    const int gtid = blockIdx.x * NTHR + tid;
    const int nth = NCTA * NTHR;

    // ---- init scratch (deterministic every launch) ----
    for (int i = gtid; i < BATCH * 2048; i += nth) (&g_hcat[0][0][0])[i] = 0.f;
    for (int i = gtid; i < BATCH * HID; i += nth) { (&g_c1[0][0])[i] = 0.f; (&g_c2[0][0])[i] = 0.f; }
    for (int i = gtid; i < G4 * HID; i += nth) {
        int r = i >> 9, k = i & 511, j = r >> 2, g = r & 3;
        g_W1r[r][k] = tf32r(Whh1[(size_t)(g * 512 + j) * 512 + k]);
    }
    for (int i = gtid; i < G4 * 1024; i += nth) {
        int r = i >> 10, k = i & 1023, j = r >> 2, g = r & 3;
        float v = (k < 512) ? Wih2[(size_t)(g * 512 + j) * 512 + k]
                            : Whh2[(size_t)(g * 512 + j) * 512 + (k - 512)];
        g_W2cat[r][k] = tf32r(v);
    }
    for (int r = gtid; r < G4; r += nth) {
        int j = r >> 2, g = r & 3;
        g_b1r[r] = bih1[g * 512 + j] + bhh1[g * 512 + j];
        g_b2r[r] = bih2[g * 512 + j] + bhh2[g * 512 + j];
        const float* s = &Wih1[(size_t)(g * 512 + j) * 4];
        float4 v = make_float4(tf32r(s[0]), tf32r(s[1]), tf32r(s[2]), tf32r(s[3]));
        float4 z = make_float4(0.f, 0.f, 0.f, 0.f);
        float4* d = (float4*)&g_W1pad[r][0];
        d[0] = v;
#pragma unroll
        for (int q = 1; q < 8; q++) d[q] = z;
    }
    for (int rb = gtid; rb < TSTEPS * BATCH; rb += nth) {
        const float* s = x + (size_t)rb * 4;
        float4 v = make_float4(tf32r(s[0]), tf32r(s[1]), tf32r(s[2]), tf32r(s[3]));
        float4 z = make_float4(0.f, 0.f, 0.f, 0.f);
        float4* d = (float4*)(&g_xpad[0][0][0] + (size_t)rb * 32);
        d[0] = v;
#pragma unroll
        for (int q = 1; q < 8; q++) d[q] = z;
    }
    grid_bar();   // full fence: weights/x now safe to cache anywhere

    // ---- group barrier setup (monotonic across graph replays) ----
    unsigned* const grp_ctr = &g_grp_cnt[blockIdx.x >> 4][0];
    unsigned bar_base = 0;
    if (tid == 0) {
        asm volatile("ld.acquire.gpu.global.u32 %0, [%1];" : "=r"(bar_base) : "l"(grp_ctr) : "memory");
    }
    unsigned phn = 0;
#define GB() group_bar(grp_ctr, bar_base + 16u * (++phn))

    // ---- dependency-exact schedule: ONE barrier per step ----
    // L1(t+1) depends only on h1(t) (same barrier that gates L2(t)); L2(t)
    // and L1(t+1) touch disjoint buffer/column ranges, so they share one
    // barrier interval. Same for FUTL2(s) + FUTA(s+1). PRE->FUTA(0) is
    // thread-private through g_prefut (each thread reads exactly what it
    // wrote), so they fuse with no sync at all.
    int p = 0;
    // step 0 head
    gemm_phase<MODE_L1>(0, 0, smem_u, &g_hcat[1][0][0], &g_c1[0][0]);
    GB();
    // intervals t = 0..126: L2(t, p) ; L1(t+1, p^1)
    for (int t = 0; t < TSTEPS - 1; t++) {
        gemm_phase<MODE_L2>(t, p, smem_u, &g_hcat[1 - p][0][512], &g_c2[0][0]);
        gemm_phase<MODE_L1>(t + 1, p ^ 1, smem_u, &g_hcat[p][0][0], &g_c1[0][0]);
        GB();
        p ^= 1;
    }
    // tail: L2(127, p=1)
    gemm_phase<MODE_L2>(TSTEPS - 1, p, smem_u, &g_hcat[1 - p][0][512], &g_c2[0][0]);
    GB();
    p ^= 1;   // p = 0: h1(127) in hcat[0][0:512], h2(127) in hcat[0][512:]

    // PRE (prefut = h2(127) @ Wih2r^T + b2r) fused with FUTA(0) — prefut is
    // thread-private between the two.
    gemm_phase<MODE_PRE>(0, p, smem_u, nullptr, nullptr);
    gemm_phase<MODE_FUTA>(0, p, smem_u, &g_hcat[1 - p][0][0], &g_c1[0][0]);
    GB();

    // future intervals s = 0..30: FUTL2(s, p) ; FUTA(s+1, p^1) ; out(s)
    for (int s = 0; s < FUTN - 1; s++) {
        gemm_phase<MODE_L2>(0, p, smem_u, &g_hcat[1 - p][0][512], &g_c2[0][0]);
        gemm_phase<MODE_FUTA>(0, p ^ 1, smem_u, &g_hcat[p][0][0], &g_c1[0][0]);
        GB();
        out_gemv(&g_hcat[1 - p][0][512], Wl, bl, out, s);
        p ^= 1;
    }
    // tail: FUTL2(31)
    gemm_phase<MODE_L2>(0, p, smem_u, &g_hcat[1 - p][0][512], &g_c2[0][0]);
    GB();
    out_gemv(&g_hcat[1 - p][0][512], Wl, bl, out, FUTN - 1);
#undef GB
}

extern "C" void kernel_launch(void* const* d_in, const int* in_sizes, int n_in,
                              void* d_out, int out_size)
{
    (void)in_sizes; (void)n_in; (void)out_size;
    cudaFuncSetAttribute(lstm_kernel, cudaFuncAttributeMaxDynamicSharedMemorySize, SMEM_BYTES);
    lstm_kernel<<<NCTA, NTHR, SMEM_BYTES>>>(
        (const float*)d_in[0],
        (const float*)d_in[1], (const float*)d_in[2],
        (const float*)d_in[3], (const float*)d_in[4],
        (const float*)d_in[5], (const float*)d_in[6],
        (const float*)d_in[7], (const float*)d_in[8],
        (const float*)d_in[9], (const float*)d_in[10],
        (float*)d_out);
}